// round 16
// baseline (speedup 1.0000x reference)
#include <cuda_runtime.h>
#include <math.h>

#define NN    4096
#define DD    64
#define T     1024
#define FULL  0xFFFFFFFFu

__device__ double       g_acc;
__device__ unsigned int g_done;

__device__ __forceinline__ float dot4(float4 a, float4 b) {
    return a.x * b.x + a.y * b.y + a.z * b.z + a.w * b.w;
}

// exp(x) for |x| <= ~85: FMA-pipe polynomial, no MUFU.
__device__ __forceinline__ float fast_exp(float x) {
    float t  = x * 1.44269504f;
    float kf = floorf(t);
    float f  = t - kf;
    float p  = 1.33988744e-3f;
    p = fmaf(p, f, 9.61843736e-3f);
    p = fmaf(p, f, 5.55033247e-2f);
    p = fmaf(p, f, 2.40226479e-1f);
    p = fmaf(p, f, 6.93147203e-1f);
    p = fmaf(p, f, 1.0f);
    int ki = (int)kf;
    return p * __int_as_float((ki + 127) << 23);
}

// NOTE: the bias b0 cancels exactly in the NLL:
//   (x_i + b0) - logsumexp_j(x_j + b0) == x_i - logsumexp_j(x_j)
// so it is never loaded or applied.

__global__ __launch_bounds__(T, 2) void fused_kernel(const float* __restrict__ X,
                                                     const float* __restrict__ W,
                                                     const int* __restrict__ rankings,
                                                     float* __restrict__ out) {
    __shared__ float s_sc[NN];
    __shared__ float s_ws[32];
    __shared__ float s_red[32];

    const int b    = blockIdx.x;
    const int tid  = threadIdx.x;
    const int grp  = tid >> 4;           // score within 64-wide stripe
    const int gl   = tid & 15;           // lane within 16-lane dot group
    const int lane = tid & 31;
    const int wrp  = tid >> 5;

    // -------- Phase 1: scores = X[b] @ W (bias cancels in the NLL) ----------
    const float4  wv = reinterpret_cast<const float4*>(W)[gl];
    const float4* Xv = reinterpret_cast<const float4*>(X + (size_t)b * NN * DD);

    #pragma unroll 2
    for (int k0 = 0; k0 < NN / 64; k0 += 4) {     // 16 iterations
        const float4 xa = Xv[(size_t)(k0 + 0) * 1024 + tid];
        const float4 xb = Xv[(size_t)(k0 + 1) * 1024 + tid];
        const float4 xc = Xv[(size_t)(k0 + 2) * 1024 + tid];
        const float4 xd = Xv[(size_t)(k0 + 3) * 1024 + tid];

        float pa = dot4(xa, wv);
        float pb = dot4(xb, wv);
        float pc = dot4(xc, wv);
        float pd = dot4(xd, wv);
        #pragma unroll
        for (int o = 8; o; o >>= 1) {
            pa += __shfl_xor_sync(FULL, pa, o);
            pb += __shfl_xor_sync(FULL, pb, o);
            pc += __shfl_xor_sync(FULL, pc, o);
            pd += __shfl_xor_sync(FULL, pd, o);
        }
        if (gl == 0) {
            s_sc[(k0 + 0) * 64 + grp] = pa;
            s_sc[(k0 + 1) * 64 + grp] = pb;
            s_sc[(k0 + 2) * 64 + grp] = pc;
            s_sc[(k0 + 3) * 64 + grp] = pd;
        }
    }

    // Rankings load overlaps the barrier wait for late warps.
    const int4 r = reinterpret_cast<const int4*>(rankings + (size_t)b * NN)[tid];
    __syncthreads();

    // -------- Phase 2: gather 4 elements (positions 4*tid .. 4*tid+3) -------
    // rankings are guaranteed in [0, NN) by the problem definition.
    const float x0 = s_sc[r.x];
    const float x1 = s_sc[r.y];
    const float x2 = s_sc[r.z];
    const float x3 = s_sc[r.w];

    // -------- Phase 3: exps on the FMA pipe (no shift: |score| << 85) --------
    const float e0 = fast_exp(x0);
    const float e1 = fast_exp(x1);
    const float e2 = fast_exp(x2);
    const float e3 = fast_exp(x3);

    // -------- Phase 4: additive suffix-sum scan ------------------------------
    float inc = (e0 + e1) + (e2 + e3);
    #pragma unroll
    for (int d = 1; d < 32; d <<= 1) {
        const float t = __shfl_down_sync(FULL, inc, d);
        if (lane + d < 32) inc += t;
    }
    if (lane == 0) s_ws[wrp] = inc;

    // Within-warp exclusive carry depends only on `inc`: issue its shuffle
    // now so the latency hides under the barrier below.
    float ex = __shfl_down_sync(FULL, inc, 1);
    ex = (lane < 31) ? ex : 0.0f;
    __syncthreads();

    if (wrp == 0) {
        float av = s_ws[lane];
        #pragma unroll
        for (int d = 1; d < 32; d <<= 1) {
            const float t = __shfl_down_sync(FULL, av, d);
            if (lane + d < 32) av += t;
        }
        s_ws[lane] = av;                         // inclusive suffix over warps lane..31
    }
    __syncthreads();

    const float Sc = ex + ((wrp < 31) ? s_ws[wrp + 1] : 0.0f);

    // -------- Phase 5: replay descending; batched exponent/mantissa log ------
    float rs    = Sc;
    int   ksum  = 0;
    float mprod = 1.0f;

    rs += e3; { int bt = __float_as_int(rs); ksum += bt >> 23; mprod *= __int_as_float((bt & 0x007FFFFF) | 0x3F000000); }
    rs += e2; { int bt = __float_as_int(rs); ksum += bt >> 23; mprod *= __int_as_float((bt & 0x007FFFFF) | 0x3F000000); }
    rs += e1; { int bt = __float_as_int(rs); ksum += bt >> 23; mprod *= __int_as_float((bt & 0x007FFFFF) | 0x3F000000); }
    rs += e0; { int bt = __float_as_int(rs); ksum += bt >> 23; mprod *= __int_as_float((bt & 0x007FFFFF) | 0x3F000000); }

    const float logsum = (float)(ksum - 4 * 126) * 0.69314718f + __logf(mprod);
    float acc = ((x0 + x1) + (x2 + x3)) - logsum;

    // -------- Phase 6: block reduce + completion-counter finalize ------------
    #pragma unroll
    for (int o = 16; o; o >>= 1) acc += __shfl_xor_sync(FULL, acc, o);
    if (lane == 0) s_red[wrp] = acc;
    __syncthreads();
    if (wrp == 0) {
        float t = s_red[lane];
        #pragma unroll
        for (int o = 16; o; o >>= 1) t += __shfl_xor_sync(FULL, t, o);
        if (lane == 0) {
            atomicAdd(&g_acc, (double)t);
            __threadfence();
            const unsigned int ticket = atomicAdd(&g_done, 1u);
            if (ticket == gridDim.x - 1) {
                out[0] = (float)(-g_acc / (double)gridDim.x);
                g_acc  = 0.0;
                g_done = 0u;
                __threadfence();
            }
        }
    }
}

extern "C" void kernel_launch(void* const* d_in, const int* in_sizes, int n_in,
                              void* d_out, int out_size) {
    const float* X        = (const float*)d_in[0];
    const float* W        = (const float*)d_in[1];
    const int*   rankings = (const int*)d_in[3];
    float* out = (float*)d_out;

    const int BN = in_sizes[3];   // B * N
    const int B  = BN / NN;

    fused_kernel<<<B, T>>>(X, W, rankings, out);
}